// round 11
// baseline (speedup 1.0000x reference)
#include <cuda_runtime.h>
#include <cuda_fp16.h>
#include <cstdint>

#define NN 100000
#define NN_PAD 100096
#define EE 1600000
#define NEDGE (EE + NN)
#define HH 128
#define GG 64
#define OUTD 32

// ---------------- scratch (device globals; zero at module load) ----------------
// Self-cleaning invariants per run: deg (zeroed by k_pool), gcnt (zeroed by
// k_scan_final blk0), pool (zeroed by k_mlp), cursor (zeroed by k_prep).
__device__ int    g_deg[NN];
__device__ float  g_dinv[NN];
__device__ int    g_rowoff[NN + 1];
__device__ int    g_cursor[NN];
__device__ int2   g_cw[NEDGE];                    // packed (col, w bits)
__device__ float  g_bufB[(size_t)NN * HH];        // layer-3 agg output (pool input)
__device__ __half g_half[(size_t)NN * HH];        // fp16 GEMM output for gather
__device__ uint2  g_Aimg[(size_t)NN_PAD * 32];    // A fp16 fragment-permuted cells {w, w+4}
__device__ uint4  g_Wiv[3 * 2560];                // W^T fp16 paired-kk cells, [128][20]
__device__ float  g_pool[GG * HH];
__device__ int    g_gcnt[GG];
__device__ int    g_goff[GG + 1];
__device__ int    g_part[128];

// ---------------- fused prep: A image + degree/graph counts + W images ---------
__global__ void k_prep(const float* __restrict__ x, const int* __restrict__ ei,
                       const int* __restrict__ batch,
                       const float* __restrict__ W1, const float* __restrict__ W2,
                       const float* __restrict__ W3) {
    int idx = blockIdx.x * blockDim.x + threadIdx.x;
    if (idx < NN * 32) {
        int row = idx >> 5, c = idx & 31;
        int w = ((c >> 2) << 3) + (c & 3);             // word index kk*8+q
        const float* xr = x + (size_t)row * 128;
        float2 p = *(const float2*)(xr + 2 * w);
        float2 s = *(const float2*)(xr + 2 * w + 8);
        __half2 hp = __floats2half2_rn(p.x, p.y);
        __half2 hs = __floats2half2_rn(s.x, s.y);
        g_Aimg[(size_t)row * 32 + c] = make_uint2(*(unsigned*)&hp, *(unsigned*)&hs);
        if (idx < NN) { g_cursor[idx] = 0; atomicAdd(&g_gcnt[batch[idx]], 1); }
        if (idx < EE) atomicAdd(&g_deg[ei[EE + idx]], 1);
    } else {
        int r = idx - NN * 32;
        if (r < 3 * 2048) {
            int l = r >> 11, rr = r & 2047;
            const float* W = (l == 0) ? W1 : (l == 1) ? W2 : W3;
            int n = rr >> 4, c = rr & 15;
            int j = c >> 2, q = c & 3;
            int ka = 32 * j + 2 * q;
            int kb = ka + 16;
            __half2 x0 = __floats2half2_rn(W[(size_t)ka * 128 + n],       W[(size_t)(ka + 1) * 128 + n]);
            __half2 y0 = __floats2half2_rn(W[(size_t)(ka + 8) * 128 + n], W[(size_t)(ka + 9) * 128 + n]);
            __half2 z0 = __floats2half2_rn(W[(size_t)kb * 128 + n],       W[(size_t)(kb + 1) * 128 + n]);
            __half2 w0 = __floats2half2_rn(W[(size_t)(kb + 8) * 128 + n], W[(size_t)(kb + 9) * 128 + n]);
            uint4 cell;
            cell.x = *(unsigned*)&x0; cell.y = *(unsigned*)&y0;
            cell.z = *(unsigned*)&z0; cell.w = *(unsigned*)&w0;
            g_Wiv[l * 2560 + n * 20 + c] = cell;
        }
    }
}

// ---------------- scans (deg counts edges only; all uses are deg+1) ------------
#define SCAN_CHUNK 1024
#define SCAN_PARTS ((NN + SCAN_CHUNK - 1) / SCAN_CHUNK)

__global__ void k_scan_part() {
    __shared__ int s[256];
    int base = blockIdx.x * SCAN_CHUNK;
    int t = threadIdx.x;
    int sum = 0;
#pragma unroll
    for (int j = 0; j < 4; j++) {
        int i = base + t + j * 256;
        if (i < NN) {
            int d = g_deg[i] + 1;
            sum += d;
            g_dinv[i] = rsqrtf((float)d);
        }
    }
    s[t] = sum; __syncthreads();
    for (int off = 128; off; off >>= 1) {
        if (t < off) s[t] += s[t + off];
        __syncthreads();
    }
    if (t == 0) g_part[blockIdx.x] = s[0];
}

// scan_final also: per-block prefix of g_part; blk0 builds goff + zeroes gcnt
__global__ void k_scan_final() {
    __shared__ int s[SCAN_CHUNK];
    __shared__ int sbase;
    int t = threadIdx.x;
    if (t == 0) {
        int b = 0;
        for (int p = 0; p < (int)blockIdx.x; p++) b += g_part[p];
        sbase = b;
        if (blockIdx.x == 0) {
            int g = 0;
            for (int qq = 0; qq < GG; qq++) {
                g_goff[qq] = g;
                g += g_gcnt[qq];
                g_gcnt[qq] = 0;            // self-clean for next run
            }
            g_goff[GG] = g;
            g_rowoff[NN] = NEDGE;
        }
    }
    int i = blockIdx.x * SCAN_CHUNK + t;
    int v = (i < NN) ? g_deg[i] + 1 : 0;
    s[t] = v; __syncthreads();
    for (int off = 1; off < SCAN_CHUNK; off <<= 1) {
        int x = (t >= off) ? s[t - off] : 0;
        __syncthreads();
        s[t] += x;
        __syncthreads();
    }
    if (i < NN) g_rowoff[i] = sbase + s[t] - v;
}

__global__ void k_fill(const int* __restrict__ ei) {
    int idx = blockIdx.x * blockDim.x + threadIdx.x;
    if (idx >= NEDGE) return;
    int s, d;
    if (idx < EE) { s = ei[idx]; d = ei[EE + idx]; }
    else          { s = d = idx - EE; }
    int pos = g_rowoff[d] + atomicAdd(&g_cursor[d], 1);
    float w = g_dinv[s] * g_dinv[d];
    g_cw[pos] = make_int2(s, __float_as_int(w));
}

// ---------------- tensor-core GEMM (mma.sync fp16, single-pass W) --------------
// block = 128x128 tile, 512 threads / 16 warps as 4 rg x 4 cg, warp = 32x32.
// 2 CTAs/SM => 32 warps resident (latency hiding); B smem stride-20 paired cells.
#define GSM 40960   // 128 rows * 20 uint4 * 16 B

#define MMA_F16(C, A0, A1, A2, A3, B0, B1) \
    asm volatile("mma.sync.aligned.m16n8k16.row.col.f32.f16.f16.f32 " \
                 "{%0,%1,%2,%3}, {%4,%5,%6,%7}, {%8,%9}, {%0,%1,%2,%3};" \
                 : "+f"((C)[0]), "+f"((C)[1]), "+f"((C)[2]), "+f"((C)[3]) \
                 : "r"(A0), "r"(A1), "r"(A2), "r"(A3), "r"(B0), "r"(B1))

__global__ void __launch_bounds__(512, 2) k_gemm_mma(int layer) {
    extern __shared__ char smem[];
    int tid = threadIdx.x;
    int row0 = blockIdx.x << 7;

    // stage B cell image: 2560 uint4 = 40 KB
    {
        const uint4* src = g_Wiv + layer * 2560;
        uint4* dst = (uint4*)smem;
#pragma unroll
        for (int it = 0; it < 5; it++) {
            int i = it * 512 + tid;
            dst[i] = __ldg(&src[i]);
        }
    }
    __syncthreads();

    const uint4* pB = (const uint4*)smem;

    int lane = tid & 31, warp = tid >> 5;
    int rq = lane >> 2;        // 0..7
    int q = lane & 3;          // 0..3
    int rg = warp & 3, cg = warp >> 2;
    int wrow = row0 + rg * 32;
    int ncol0 = cg * 32;

    float c[2][4][4] = {};

    int aidx = (wrow + rq) * 32 + q;       // +8 per j; rows step 256 cells
    int bidx = (ncol0 + rq) * 20 + q;      // +4 per j; n-blocks step 160

#pragma unroll
    for (int j = 0; j < 4; j++) {
        uint2 Aa0 = g_Aimg[aidx],       Aa1 = g_Aimg[aidx + 256];
        uint2 Aa2 = g_Aimg[aidx + 512], Aa3 = g_Aimg[aidx + 768];
        uint2 Ab0 = g_Aimg[aidx + 4],   Ab1 = g_Aimg[aidx + 260];
        uint2 Ab2 = g_Aimg[aidx + 516], Ab3 = g_Aimg[aidx + 772];
#pragma unroll
        for (int t = 0; t < 4; t++) {
            uint4 B = pB[bidx + t * 160];
            MMA_F16(c[0][t], Aa0.x, Aa1.x, Aa0.y, Aa1.y, B.x, B.y);
            MMA_F16(c[1][t], Aa2.x, Aa3.x, Aa2.y, Aa3.y, B.x, B.y);
            MMA_F16(c[0][t], Ab0.x, Ab1.x, Ab0.y, Ab1.y, B.z, B.w);
            MMA_F16(c[1][t], Ab2.x, Ab3.x, Ab2.y, Ab3.y, B.z, B.w);
        }
        aidx += 8; bidx += 4;
    }

    // epilogue: fp16 stores straight from fragments
    unsigned short* gh = (unsigned short*)g_half;
#pragma unroll
    for (int mb = 0; mb < 2; mb++) {
        int r1 = wrow + mb * 16 + rq, r2 = r1 + 8;
#pragma unroll
        for (int t = 0; t < 4; t++) {
            int col = ncol0 + t * 8 + q * 2;
            if (r1 < NN) {
                __half2 h = __floats2half2_rn(c[mb][t][0], c[mb][t][1]);
                *(unsigned*)(gh + (size_t)r1 * 128 + col) = *(unsigned*)&h;
            }
            if (r2 < NN) {
                __half2 h = __floats2half2_rn(c[mb][t][2], c[mb][t][3]);
                *(unsigned*)(gh + (size_t)r2 * 128 + col) = *(unsigned*)&h;
            }
        }
    }
}

// ---------------- CSR aggregation from fp16 features ----------------------------
// mode 0: relu, write fp16 A image (GEMM input). mode 1: no relu, write fp32 bufB.
__global__ void k_agg_h(const float* __restrict__ bias, int mode) {
    int row = (blockIdx.x * blockDim.x + threadIdx.x) >> 5;
    int lane = threadIdx.x & 31;
    if (row >= NN) return;
    int beg = g_rowoff[row];
    int end = g_rowoff[row + 1];
    const uint2* T = (const uint2*)g_half;
    float4 acc0 = make_float4(0.f, 0.f, 0.f, 0.f);
    float4 acc1 = make_float4(0.f, 0.f, 0.f, 0.f);
    int e = beg;
    for (; e + 3 < end; e += 4) {
        int2 cw0 = g_cw[e],     cw1 = g_cw[e + 1];
        int2 cw2 = g_cw[e + 2], cw3 = g_cw[e + 3];
        uint2 u0 = __ldg(&T[(size_t)cw0.x * 32 + lane]);
        uint2 u1 = __ldg(&T[(size_t)cw1.x * 32 + lane]);
        uint2 u2 = __ldg(&T[(size_t)cw2.x * 32 + lane]);
        uint2 u3 = __ldg(&T[(size_t)cw3.x * 32 + lane]);
        float w0 = __int_as_float(cw0.y), w1 = __int_as_float(cw1.y);
        float w2 = __int_as_float(cw2.y), w3 = __int_as_float(cw3.y);
        float2 a0 = __half22float2(*(__half2*)&u0.x), b0 = __half22float2(*(__half2*)&u0.y);
        float2 a1 = __half22float2(*(__half2*)&u1.x), b1 = __half22float2(*(__half2*)&u1.y);
        float2 a2 = __half22float2(*(__half2*)&u2.x), b2 = __half22float2(*(__half2*)&u2.y);
        float2 a3 = __half22float2(*(__half2*)&u3.x), b3 = __half22float2(*(__half2*)&u3.y);
        acc0.x = fmaf(w0, a0.x, acc0.x); acc0.y = fmaf(w0, a0.y, acc0.y);
        acc0.z = fmaf(w0, b0.x, acc0.z); acc0.w = fmaf(w0, b0.y, acc0.w);
        acc1.x = fmaf(w1, a1.x, acc1.x); acc1.y = fmaf(w1, a1.y, acc1.y);
        acc1.z = fmaf(w1, b1.x, acc1.z); acc1.w = fmaf(w1, b1.y, acc1.w);
        acc0.x = fmaf(w2, a2.x, acc0.x); acc0.y = fmaf(w2, a2.y, acc0.y);
        acc0.z = fmaf(w2, b2.x, acc0.z); acc0.w = fmaf(w2, b2.y, acc0.w);
        acc1.x = fmaf(w3, a3.x, acc1.x); acc1.y = fmaf(w3, a3.y, acc1.y);
        acc1.z = fmaf(w3, b3.x, acc1.z); acc1.w = fmaf(w3, b3.y, acc1.w);
    }
    for (; e < end; e++) {
        int2 cw = g_cw[e];
        float w = __int_as_float(cw.y);
        uint2 u = __ldg(&T[(size_t)cw.x * 32 + lane]);
        float2 a = __half22float2(*(__half2*)&u.x);
        float2 b = __half22float2(*(__half2*)&u.y);
        acc0.x = fmaf(w, a.x, acc0.x); acc0.y = fmaf(w, a.y, acc0.y);
        acc0.z = fmaf(w, b.x, acc0.z); acc0.w = fmaf(w, b.y, acc0.w);
    }
    float4 b4 = ((const float4*)bias)[lane];
    float4 r;
    r.x = acc0.x + acc1.x + b4.x;
    r.y = acc0.y + acc1.y + b4.y;
    r.z = acc0.z + acc1.z + b4.z;
    r.w = acc0.w + acc1.w + b4.w;
    if (mode == 0) {
        r.x = fmaxf(r.x, 0.f); r.y = fmaxf(r.y, 0.f);
        r.z = fmaxf(r.z, 0.f); r.w = fmaxf(r.w, 0.f);
        // assemble this lane's A-image cell via shfl (lane = cell index)
        __half2 h01 = __floats2half2_rn(r.x, r.y);
        __half2 h23 = __floats2half2_rn(r.z, r.w);
        unsigned w01 = *(unsigned*)&h01, w23 = *(unsigned*)&h23;
        int kk = lane >> 2, q = lane & 3;
        int lA = 4 * kk + (q >> 1);
        int lB = lA + 2;
        unsigned a01 = __shfl_sync(0xFFFFFFFFu, w01, lA);
        unsigned a23 = __shfl_sync(0xFFFFFFFFu, w23, lA);
        unsigned b01 = __shfl_sync(0xFFFFFFFFu, w01, lB);
        unsigned b23 = __shfl_sync(0xFFFFFFFFu, w23, lB);
        unsigned wa = (q & 1) ? a23 : a01;
        unsigned wb = (q & 1) ? b23 : b01;
        g_Aimg[(size_t)row * 32 + lane] = make_uint2(wa, wb);
    } else {
        ((float4*)g_bufB)[(size_t)row * 32 + lane] = r;
    }
}

// ---------------- pooling (+ deg/cursor cleanup for next run) -------------------
__global__ void k_pool() {
    int gid = blockIdx.x * 128 + threadIdx.x;
    for (int i = gid; i < NN; i += 512 * 128) { g_deg[i] = 0; }
    int g = blockIdx.x >> 3;
    int s = blockIdx.x & 7;
    int col = threadIdx.x;
    int start = g_goff[g];
    int cnt = g_goff[g + 1] - start;
    int chunk = (cnt + 7) >> 3;
    int lo = start + s * chunk;
    int hi = lo + chunk;
    int ge = start + cnt;
    if (hi > ge) hi = ge;
    float sum = 0.f;
    int i = lo;
    for (; i + 3 < hi; i += 4) {
        sum += g_bufB[(size_t)(i + 0) * 128 + col];
        sum += g_bufB[(size_t)(i + 1) * 128 + col];
        sum += g_bufB[(size_t)(i + 2) * 128 + col];
        sum += g_bufB[(size_t)(i + 3) * 128 + col];
    }
    for (; i < hi; i++) sum += g_bufB[(size_t)i * 128 + col];
    if (lo < hi) atomicAdd(&g_pool[g * 128 + col], sum);
}

// ---------------- MLP head (+ pool cleanup for next run) ------------------------
__global__ void k_mlp(const float* __restrict__ Wo1, const float* __restrict__ bo1,
                      const float* __restrict__ Wo2, const float* __restrict__ bo2,
                      float* __restrict__ out) {
    __shared__ float ps[128];
    __shared__ float zs[64];
    int g = blockIdx.x;
    int t = threadIdx.x;
    int cnt = g_goff[g + 1] - g_goff[g];
    float inv = 1.0f / fmaxf((float)cnt, 1.0f);
    ps[t]      = g_pool[g * 128 + t] * inv;
    ps[t + 64] = g_pool[g * 128 + t + 64] * inv;
    g_pool[g * 128 + t] = 0.f;          // self-clean for next run
    g_pool[g * 128 + t + 64] = 0.f;
    __syncthreads();
    float z = bo1[t];
#pragma unroll 8
    for (int k = 0; k < 128; k++) z = fmaf(ps[k], Wo1[k * 64 + t], z);
    zs[t] = fmaxf(z, 0.f);
    __syncthreads();
    if (t < OUTD) {
        float o = bo2[t];
#pragma unroll 8
        for (int j = 0; j < 64; j++) o = fmaf(zs[j], Wo2[j * 32 + t], o);
        out[g * OUTD + t] = o;
    }
}

// ---------------- launch ------------------------------------------------------------
extern "C" void kernel_launch(void* const* d_in, const int* in_sizes, int n_in,
                              void* d_out, int out_size) {
    const float* x    = (const float*)d_in[0];
    const int*   ei   = (const int*)d_in[1];
    const int*   batch= (const int*)d_in[2];
    const float* W1   = (const float*)d_in[3];
    const float* b1   = (const float*)d_in[4];
    const float* W2   = (const float*)d_in[5];
    const float* b2   = (const float*)d_in[6];
    const float* W3   = (const float*)d_in[7];
    const float* b3   = (const float*)d_in[8];
    const float* Wo1  = (const float*)d_in[9];
    const float* bo1  = (const float*)d_in[10];
    const float* Wo2  = (const float*)d_in[11];
    const float* bo2  = (const float*)d_in[12];
    float* out = (float*)d_out;

    cudaFuncSetAttribute(k_gemm_mma, cudaFuncAttributeMaxDynamicSharedMemorySize, GSM);

    const int PREP_TASKS = NN * 32 + 3 * 2048;
    const int GEMM_BLOCKS = (NN + 127) / 128;   // 782 -> covers NN_PAD rows
    const int AGG_BLOCKS  = (NN + 7) / 8;

    k_prep<<<(PREP_TASKS + 255) / 256, 256>>>(x, ei, batch, W1, W2, W3);  // 0
    k_scan_part<<<SCAN_PARTS, 256>>>();                                   // 1
    k_scan_final<<<SCAN_PARTS, SCAN_CHUNK>>>();                           // 2
    k_gemm_mma<<<GEMM_BLOCKS, 512, GSM>>>(0);                             // 3 <- ncu slot
    k_fill<<<(NEDGE + 255) / 256, 256>>>(ei);                             // 4

    k_agg_h<<<AGG_BLOCKS, 256>>>(b1, 0);                                  // 5
    k_gemm_mma<<<GEMM_BLOCKS, 512, GSM>>>(1);                             // 6
    k_agg_h<<<AGG_BLOCKS, 256>>>(b2, 0);                                  // 7
    k_gemm_mma<<<GEMM_BLOCKS, 512, GSM>>>(2);                             // 8
    k_agg_h<<<AGG_BLOCKS, 256>>>(b3, 1);                                  // 9

    k_pool<<<GG * 8, 128>>>();                                            // 10
    k_mlp<<<GG, 64>>>(Wo1, bo1, Wo2, bo2, out);                           // 11
}

// round 12
// speedup vs baseline: 1.1047x; 1.1047x over previous
#include <cuda_runtime.h>
#include <cuda_fp16.h>
#include <cstdint>

#define NN 100000
#define NN_PAD 100096
#define EE 1600000
#define NEDGE (EE + NN)
#define HH 128
#define GG 64
#define OUTD 32

// ---------------- scratch (device globals; zero at module load) ----------------
// Self-cleaning per run: deg (zeroed by k_pool), gcnt (zeroed by k_scan_final
// blk0), pool (zeroed by k_mlp), cursor (zeroed by k_prep).
__device__ int    g_deg[NN];
__device__ float  g_dinv[NN];
__device__ int    g_rowoff[NN + 1];
__device__ int    g_cursor[NN];
__device__ int2   g_cw[NEDGE];                    // packed (col, w bits)
__device__ float  g_bufB[(size_t)NN * HH];        // layer-3 agg output (pool input)
__device__ __half g_half[(size_t)NN * HH];        // fp16 GEMM output for gather
__device__ uint2  g_Aimg[(size_t)NN_PAD * 32];    // A fp16 fragment-permuted cells {w, w+4}
__device__ uint4  g_Wiv[3 * 2560];                // W^T fp16 paired-kk cells, [128][20]
__device__ float  g_pool[GG * HH];
__device__ int    g_gcnt[GG];
__device__ int    g_goff[GG + 1];
__device__ int    g_part[128];

// ---------------- fused prep: A image + degree/graph counts + W images ---------
__global__ void k_prep(const float* __restrict__ x, const int* __restrict__ ei,
                       const int* __restrict__ batch,
                       const float* __restrict__ W1, const float* __restrict__ W2,
                       const float* __restrict__ W3) {
    int idx = blockIdx.x * blockDim.x + threadIdx.x;
    if (idx < NN * 32) {
        int row = idx >> 5, c = idx & 31;
        int w = ((c >> 2) << 3) + (c & 3);             // word index kk*8+q
        const float* xr = x + (size_t)row * 128;
        float2 p = *(const float2*)(xr + 2 * w);
        float2 s = *(const float2*)(xr + 2 * w + 8);
        __half2 hp = __floats2half2_rn(p.x, p.y);
        __half2 hs = __floats2half2_rn(s.x, s.y);
        g_Aimg[(size_t)row * 32 + c] = make_uint2(*(unsigned*)&hp, *(unsigned*)&hs);
        if (idx < NN) { g_cursor[idx] = 0; atomicAdd(&g_gcnt[batch[idx]], 1); }
        if (idx < EE) atomicAdd(&g_deg[ei[EE + idx]], 1);
    } else {
        int r = idx - NN * 32;
        if (r < 3 * 2048) {
            int l = r >> 11, rr = r & 2047;
            const float* W = (l == 0) ? W1 : (l == 1) ? W2 : W3;
            int n = rr >> 4, c = rr & 15;
            int j = c >> 2, q = c & 3;
            int ka = 32 * j + 2 * q;
            int kb = ka + 16;
            __half2 x0 = __floats2half2_rn(W[(size_t)ka * 128 + n],       W[(size_t)(ka + 1) * 128 + n]);
            __half2 y0 = __floats2half2_rn(W[(size_t)(ka + 8) * 128 + n], W[(size_t)(ka + 9) * 128 + n]);
            __half2 z0 = __floats2half2_rn(W[(size_t)kb * 128 + n],       W[(size_t)(kb + 1) * 128 + n]);
            __half2 w0 = __floats2half2_rn(W[(size_t)(kb + 8) * 128 + n], W[(size_t)(kb + 9) * 128 + n]);
            uint4 cell;
            cell.x = *(unsigned*)&x0; cell.y = *(unsigned*)&y0;
            cell.z = *(unsigned*)&z0; cell.w = *(unsigned*)&w0;
            g_Wiv[l * 2560 + n * 20 + c] = cell;
        }
    }
}

// ---------------- scans (deg counts edges only; all uses are deg+1) ------------
#define SCAN_CHUNK 1024
#define SCAN_PARTS ((NN + SCAN_CHUNK - 1) / SCAN_CHUNK)

__global__ void k_scan_part() {
    __shared__ int s[256];
    int base = blockIdx.x * SCAN_CHUNK;
    int t = threadIdx.x;
    int sum = 0;
#pragma unroll
    for (int j = 0; j < 4; j++) {
        int i = base + t + j * 256;
        if (i < NN) {
            int d = g_deg[i] + 1;
            sum += d;
            g_dinv[i] = rsqrtf((float)d);
        }
    }
    s[t] = sum; __syncthreads();
    for (int off = 128; off; off >>= 1) {
        if (t < off) s[t] += s[t + off];
        __syncthreads();
    }
    if (t == 0) g_part[blockIdx.x] = s[0];
}

// scan_final also: per-block prefix of g_part; blk0 builds goff + zeroes gcnt
__global__ void k_scan_final() {
    __shared__ int s[SCAN_CHUNK];
    __shared__ int sbase;
    int t = threadIdx.x;
    if (t == 0) {
        int b = 0;
        for (int p = 0; p < (int)blockIdx.x; p++) b += g_part[p];
        sbase = b;
        if (blockIdx.x == 0) {
            int g = 0;
            for (int qq = 0; qq < GG; qq++) {
                g_goff[qq] = g;
                g += g_gcnt[qq];
                g_gcnt[qq] = 0;            // self-clean for next run
            }
            g_goff[GG] = g;
            g_rowoff[NN] = NEDGE;
        }
    }
    int i = blockIdx.x * SCAN_CHUNK + t;
    int v = (i < NN) ? g_deg[i] + 1 : 0;
    s[t] = v; __syncthreads();
    for (int off = 1; off < SCAN_CHUNK; off <<= 1) {
        int x = (t >= off) ? s[t - off] : 0;
        __syncthreads();
        s[t] += x;
        __syncthreads();
    }
    if (i < NN) g_rowoff[i] = sbase + s[t] - v;
}

__global__ void k_fill(const int* __restrict__ ei) {
    int idx = blockIdx.x * blockDim.x + threadIdx.x;
    if (idx >= NEDGE) return;
    int s, d;
    if (idx < EE) { s = ei[idx]; d = ei[EE + idx]; }
    else          { s = d = idx - EE; }
    int pos = g_rowoff[d] + atomicAdd(&g_cursor[d], 1);
    float w = g_dinv[s] * g_dinv[d];
    g_cw[pos] = make_int2(s, __float_as_int(w));
}

// ---------------- tensor-core GEMM (mma.sync fp16, single-pass W) --------------
// block = 128x128 tile, 256 threads / 8 warps as 4 rg x 2 cg, warp = 32x64.
// BOTH operands staged in smem: A 32KB (XOR-swizzled cells), B 40KB (stride 20).
// Inner loop is pure LDS (conflict-free) -> latency trivially hidden.
#define SM_B_OFF 32768
#define GSM (32768 + 40960)   // 72 KB/CTA; 2 CTAs/SM

#define MMA_F16(C, A0, A1, A2, A3, B0, B1) \
    asm volatile("mma.sync.aligned.m16n8k16.row.col.f32.f16.f16.f32 " \
                 "{%0,%1,%2,%3}, {%4,%5,%6,%7}, {%8,%9}, {%0,%1,%2,%3};" \
                 : "+f"((C)[0]), "+f"((C)[1]), "+f"((C)[2]), "+f"((C)[3]) \
                 : "r"(A0), "r"(A1), "r"(A2), "r"(A3), "r"(B0), "r"(B1))

__global__ void __launch_bounds__(256, 2) k_gemm_mma(int layer) {
    extern __shared__ char smem[];
    uint2* sA = (uint2*)smem;                    // 4096 uint2, swizzled cells
    const uint4* pB = (const uint4*)(smem + SM_B_OFF);
    int tid = threadIdx.x;
    int row0 = blockIdx.x << 7;

    // stage B cell image: 2560 uint4 = 40 KB
    {
        const uint4* src = g_Wiv + layer * 2560;
        uint4* dst = (uint4*)(smem + SM_B_OFF);
#pragma unroll
        for (int it = 0; it < 10; it++) {
            int i = it * 256 + tid;
            dst[i] = __ldg(&src[i]);
        }
    }
    // stage A tile: 2048 uint4 = 32 KB, swizzle cell kk ^= row&7
    {
        const uint4* src = (const uint4*)(g_Aimg + (size_t)row0 * 32);
#pragma unroll
        for (int it = 0; it < 8; it++) {
            int i = it * 256 + tid;              // uint4 = 2 cells
            uint4 v = __ldg(&src[i]);
            int r = i >> 4;
            int c2 = (i & 15) * 2;               // even cell index
            int kk = c2 >> 2, q = c2 & 3;        // q in {0,2}
            int dstc = ((kk ^ (r & 7)) << 2) + q;
            *(uint4*)&sA[r * 32 + dstc] = v;
        }
    }
    __syncthreads();

    int lane = tid & 31, warp = tid >> 5;
    int rq = lane >> 2;        // 0..7
    int q = lane & 3;          // 0..3
    int rg = warp >> 1, cg = warp & 1;
    int wr = rg * 32 + rq;     // tile row of m-block 0; (row & 7) == rq
    int ncol0 = cg * 64;

    float c[2][8][4] = {};

    const uint2* aRow0 = sA + (wr +  0) * 32 + q;
    const uint2* aRow1 = sA + (wr +  8) * 32 + q;
    const uint2* aRow2 = sA + (wr + 16) * 32 + q;
    const uint2* aRow3 = sA + (wr + 24) * 32 + q;
    const uint4* bBase = pB + (ncol0 + rq) * 20 + q;

#pragma unroll
    for (int j = 0; j < 4; j++) {
        int swa = ((2 * j) ^ rq) << 2;           // swizzled cell group, kk=2j
        int swb = ((2 * j + 1) ^ rq) << 2;       // kk=2j+1
        uint2 Aa0 = aRow0[swa], Aa1 = aRow1[swa];
        uint2 Aa2 = aRow2[swa], Aa3 = aRow3[swa];
        uint2 Ab0 = aRow0[swb], Ab1 = aRow1[swb];
        uint2 Ab2 = aRow2[swb], Ab3 = aRow3[swb];
        const uint4* bp = bBase + j * 4;
#pragma unroll
        for (int t = 0; t < 8; t++) {
            uint4 B = bp[t * 8 * 20];
            MMA_F16(c[0][t], Aa0.x, Aa1.x, Aa0.y, Aa1.y, B.x, B.y);
            MMA_F16(c[1][t], Aa2.x, Aa3.x, Aa2.y, Aa3.y, B.x, B.y);
            MMA_F16(c[0][t], Ab0.x, Ab1.x, Ab0.y, Ab1.y, B.z, B.w);
            MMA_F16(c[1][t], Ab2.x, Ab3.x, Ab2.y, Ab3.y, B.z, B.w);
        }
    }

    // epilogue: fp16 stores straight from fragments
    unsigned short* gh = (unsigned short*)g_half;
    int wrow = row0 + rg * 32;
#pragma unroll
    for (int mb = 0; mb < 2; mb++) {
        int r1 = wrow + mb * 16 + rq, r2 = r1 + 8;
#pragma unroll
        for (int t = 0; t < 8; t++) {
            int col = ncol0 + t * 8 + q * 2;
            if (r1 < NN) {
                __half2 h = __floats2half2_rn(c[mb][t][0], c[mb][t][1]);
                *(unsigned*)(gh + (size_t)r1 * 128 + col) = *(unsigned*)&h;
            }
            if (r2 < NN) {
                __half2 h = __floats2half2_rn(c[mb][t][2], c[mb][t][3]);
                *(unsigned*)(gh + (size_t)r2 * 128 + col) = *(unsigned*)&h;
            }
        }
    }
}

// ---------------- CSR aggregation from fp16 features ----------------------------
// mode 0: relu, write fp16 A image (GEMM input). mode 1: no relu, write fp32 bufB.
__global__ void k_agg_h(const float* __restrict__ bias, int mode) {
    int row = (blockIdx.x * blockDim.x + threadIdx.x) >> 5;
    int lane = threadIdx.x & 31;
    if (row >= NN) return;
    int beg = g_rowoff[row];
    int end = g_rowoff[row + 1];
    const uint2* T = (const uint2*)g_half;
    float4 acc0 = make_float4(0.f, 0.f, 0.f, 0.f);
    float4 acc1 = make_float4(0.f, 0.f, 0.f, 0.f);
    int e = beg;
    for (; e + 3 < end; e += 4) {
        int2 cw0 = g_cw[e],     cw1 = g_cw[e + 1];
        int2 cw2 = g_cw[e + 2], cw3 = g_cw[e + 3];
        uint2 u0 = __ldg(&T[(size_t)cw0.x * 32 + lane]);
        uint2 u1 = __ldg(&T[(size_t)cw1.x * 32 + lane]);
        uint2 u2 = __ldg(&T[(size_t)cw2.x * 32 + lane]);
        uint2 u3 = __ldg(&T[(size_t)cw3.x * 32 + lane]);
        float w0 = __int_as_float(cw0.y), w1 = __int_as_float(cw1.y);
        float w2 = __int_as_float(cw2.y), w3 = __int_as_float(cw3.y);
        float2 a0 = __half22float2(*(__half2*)&u0.x), b0 = __half22float2(*(__half2*)&u0.y);
        float2 a1 = __half22float2(*(__half2*)&u1.x), b1 = __half22float2(*(__half2*)&u1.y);
        float2 a2 = __half22float2(*(__half2*)&u2.x), b2 = __half22float2(*(__half2*)&u2.y);
        float2 a3 = __half22float2(*(__half2*)&u3.x), b3 = __half22float2(*(__half2*)&u3.y);
        acc0.x = fmaf(w0, a0.x, acc0.x); acc0.y = fmaf(w0, a0.y, acc0.y);
        acc0.z = fmaf(w0, b0.x, acc0.z); acc0.w = fmaf(w0, b0.y, acc0.w);
        acc1.x = fmaf(w1, a1.x, acc1.x); acc1.y = fmaf(w1, a1.y, acc1.y);
        acc1.z = fmaf(w1, b1.x, acc1.z); acc1.w = fmaf(w1, b1.y, acc1.w);
        acc0.x = fmaf(w2, a2.x, acc0.x); acc0.y = fmaf(w2, a2.y, acc0.y);
        acc0.z = fmaf(w2, b2.x, acc0.z); acc0.w = fmaf(w2, b2.y, acc0.w);
        acc1.x = fmaf(w3, a3.x, acc1.x); acc1.y = fmaf(w3, a3.y, acc1.y);
        acc1.z = fmaf(w3, b3.x, acc1.z); acc1.w = fmaf(w3, b3.y, acc1.w);
    }
    for (; e < end; e++) {
        int2 cw = g_cw[e];
        float w = __int_as_float(cw.y);
        uint2 u = __ldg(&T[(size_t)cw.x * 32 + lane]);
        float2 a = __half22float2(*(__half2*)&u.x);
        float2 b = __half22float2(*(__half2*)&u.y);
        acc0.x = fmaf(w, a.x, acc0.x); acc0.y = fmaf(w, a.y, acc0.y);
        acc0.z = fmaf(w, b.x, acc0.z); acc0.w = fmaf(w, b.y, acc0.w);
    }
    float4 b4 = ((const float4*)bias)[lane];
    float4 r;
    r.x = acc0.x + acc1.x + b4.x;
    r.y = acc0.y + acc1.y + b4.y;
    r.z = acc0.z + acc1.z + b4.z;
    r.w = acc0.w + acc1.w + b4.w;
    if (mode == 0) {
        r.x = fmaxf(r.x, 0.f); r.y = fmaxf(r.y, 0.f);
        r.z = fmaxf(r.z, 0.f); r.w = fmaxf(r.w, 0.f);
        // assemble this lane's A-image cell via shfl (lane = cell index)
        __half2 h01 = __floats2half2_rn(r.x, r.y);
        __half2 h23 = __floats2half2_rn(r.z, r.w);
        unsigned w01 = *(unsigned*)&h01, w23 = *(unsigned*)&h23;
        int kk = lane >> 2, q = lane & 3;
        int lA = 4 * kk + (q >> 1);
        int lB = lA + 2;
        unsigned a01 = __shfl_sync(0xFFFFFFFFu, w01, lA);
        unsigned a23 = __shfl_sync(0xFFFFFFFFu, w23, lA);
        unsigned b01 = __shfl_sync(0xFFFFFFFFu, w01, lB);
        unsigned b23 = __shfl_sync(0xFFFFFFFFu, w23, lB);
        unsigned wa = (q & 1) ? a23 : a01;
        unsigned wb = (q & 1) ? b23 : b01;
        g_Aimg[(size_t)row * 32 + lane] = make_uint2(wa, wb);
    } else {
        ((float4*)g_bufB)[(size_t)row * 32 + lane] = r;
    }
}

// ---------------- pooling (+ deg cleanup for next run) --------------------------
__global__ void k_pool() {
    int gid = blockIdx.x * 128 + threadIdx.x;
    for (int i = gid; i < NN; i += 512 * 128) { g_deg[i] = 0; }
    int g = blockIdx.x >> 3;
    int s = blockIdx.x & 7;
    int col = threadIdx.x;
    int start = g_goff[g];
    int cnt = g_goff[g + 1] - start;
    int chunk = (cnt + 7) >> 3;
    int lo = start + s * chunk;
    int hi = lo + chunk;
    int ge = start + cnt;
    if (hi > ge) hi = ge;
    float sum = 0.f;
    int i = lo;
    for (; i + 3 < hi; i += 4) {
        sum += g_bufB[(size_t)(i + 0) * 128 + col];
        sum += g_bufB[(size_t)(i + 1) * 128 + col];
        sum += g_bufB[(size_t)(i + 2) * 128 + col];
        sum += g_bufB[(size_t)(i + 3) * 128 + col];
    }
    for (; i < hi; i++) sum += g_bufB[(size_t)i * 128 + col];
    if (lo < hi) atomicAdd(&g_pool[g * 128 + col], sum);
}

// ---------------- MLP head (+ pool cleanup for next run) ------------------------
__global__ void k_mlp(const float* __restrict__ Wo1, const float* __restrict__ bo1,
                      const float* __restrict__ Wo2, const float* __restrict__ bo2,
                      float* __restrict__ out) {
    __shared__ float ps[128];
    __shared__ float zs[64];
    int g = blockIdx.x;
    int t = threadIdx.x;
    int cnt = g_goff[g + 1] - g_goff[g];
    float inv = 1.0f / fmaxf((float)cnt, 1.0f);
    ps[t]      = g_pool[g * 128 + t] * inv;
    ps[t + 64] = g_pool[g * 128 + t + 64] * inv;
    g_pool[g * 128 + t] = 0.f;          // self-clean for next run
    g_pool[g * 128 + t + 64] = 0.f;
    __syncthreads();
    float z = bo1[t];
#pragma unroll 8
    for (int k = 0; k < 128; k++) z = fmaf(ps[k], Wo1[k * 64 + t], z);
    zs[t] = fmaxf(z, 0.f);
    __syncthreads();
    if (t < OUTD) {
        float o = bo2[t];
#pragma unroll 8
        for (int j = 0; j < 64; j++) o = fmaf(zs[j], Wo2[j * 32 + t], o);
        out[g * OUTD + t] = o;
    }
}

// ---------------- launch ------------------------------------------------------------
extern "C" void kernel_launch(void* const* d_in, const int* in_sizes, int n_in,
                              void* d_out, int out_size) {
    const float* x    = (const float*)d_in[0];
    const int*   ei   = (const int*)d_in[1];
    const int*   batch= (const int*)d_in[2];
    const float* W1   = (const float*)d_in[3];
    const float* b1   = (const float*)d_in[4];
    const float* W2   = (const float*)d_in[5];
    const float* b2   = (const float*)d_in[6];
    const float* W3   = (const float*)d_in[7];
    const float* b3   = (const float*)d_in[8];
    const float* Wo1  = (const float*)d_in[9];
    const float* bo1  = (const float*)d_in[10];
    const float* Wo2  = (const float*)d_in[11];
    const float* bo2  = (const float*)d_in[12];
    float* out = (float*)d_out;

    cudaFuncSetAttribute(k_gemm_mma, cudaFuncAttributeMaxDynamicSharedMemorySize, GSM);

    const int PREP_TASKS = NN * 32 + 3 * 2048;
    const int GEMM_BLOCKS = (NN + 127) / 128;   // 782 -> covers NN_PAD rows exactly
    const int AGG_BLOCKS  = (NN + 7) / 8;

    k_prep<<<(PREP_TASKS + 255) / 256, 256>>>(x, ei, batch, W1, W2, W3);  // 0
    k_scan_part<<<SCAN_PARTS, 256>>>();                                   // 1
    k_scan_final<<<SCAN_PARTS, SCAN_CHUNK>>>();                           // 2
    k_gemm_mma<<<GEMM_BLOCKS, 256, GSM>>>(0);                             // 3 <- ncu slot
    k_fill<<<(NEDGE + 255) / 256, 256>>>(ei);                             // 4

    k_agg_h<<<AGG_BLOCKS, 256>>>(b1, 0);                                  // 5
    k_gemm_mma<<<GEMM_BLOCKS, 256, GSM>>>(1);                             // 6
    k_agg_h<<<AGG_BLOCKS, 256>>>(b2, 0);                                  // 7
    k_gemm_mma<<<GEMM_BLOCKS, 256, GSM>>>(2);                             // 8
    k_agg_h<<<AGG_BLOCKS, 256>>>(b3, 1);                                  // 9

    k_pool<<<GG * 8, 128>>>();                                            // 10
    k_mlp<<<GG, 64>>>(Wo1, bo1, Wo2, bo2, out);                           // 11
}

// round 14
// speedup vs baseline: 1.1432x; 1.0348x over previous
#include <cuda_runtime.h>
#include <cuda_fp16.h>
#include <cstdint>

#define NN 100000
#define NN_PAD 100096
#define EE 1600000
#define NEDGE (EE + NN)
#define HH 128
#define GG 64
#define OUTD 32

// ---------------- scratch (device globals; zero at module load) ----------------
// Self-cleaning per run: deg (k_pool), gcnt (k_scan blk0), pool (k_mlp),
// cursor (k_prep), aggflag (k_fill). Aimg pad rows: never written, stay zero.
__device__ int    g_deg[NN];
__device__ float  g_dinv[NN];
__device__ int    g_rowoff[NN + 1];
__device__ int    g_cursor[NN];
__device__ int2   g_cw[NEDGE];                    // packed (col, w bits)
__device__ float  g_bufB[(size_t)NN * HH];        // layer-3 GEMM output (pool input)
__device__ __half g_half[(size_t)NN * HH];        // fp16 features for gather
__device__ uint2  g_Aimg[(size_t)NN_PAD * 32];    // agg out: fp16 fragment-permuted cells
__device__ uint4  g_Wiv[3 * 2560];                // W^T fp16 paired-kk cells, [128][20]
__device__ float  g_pool[GG * HH];
__device__ int    g_gcnt[GG];
__device__ int    g_goff[GG + 1];
__device__ volatile int g_aggval[128];
__device__ volatile int g_aggflag[128];

// ---------------- fused prep: g_half = fp16(x) + counts + W images -------------
__global__ void k_prep(const float* __restrict__ x, const int* __restrict__ ei,
                       const int* __restrict__ batch,
                       const float* __restrict__ W1, const float* __restrict__ W2,
                       const float* __restrict__ W3) {
    int idx = blockIdx.x * blockDim.x + threadIdx.x;
    if (idx < NN * 32) {
        int row = idx >> 5, c = idx & 31;
        const float4* xr4 = (const float4*)(x + (size_t)row * 128);
        float4 v = xr4[c];
        __half2 h0 = __floats2half2_rn(v.x, v.y);
        __half2 h1 = __floats2half2_rn(v.z, v.w);
        ((uint2*)g_half)[(size_t)row * 32 + c] = make_uint2(*(unsigned*)&h0, *(unsigned*)&h1);
        if (idx < NN) { g_cursor[idx] = 0; atomicAdd(&g_gcnt[batch[idx]], 1); }
        if (idx < EE) atomicAdd(&g_deg[ei[EE + idx]], 1);
    } else {
        int r = idx - NN * 32;
        if (r < 3 * 2048) {
            int l = r >> 11, rr = r & 2047;
            const float* W = (l == 0) ? W1 : (l == 1) ? W2 : W3;
            int n = rr >> 4, c = rr & 15;
            int j = c >> 2, q = c & 3;
            int ka = 32 * j + 2 * q;
            int kb = ka + 16;
            __half2 x0 = __floats2half2_rn(W[(size_t)ka * 128 + n],       W[(size_t)(ka + 1) * 128 + n]);
            __half2 y0 = __floats2half2_rn(W[(size_t)(ka + 8) * 128 + n], W[(size_t)(ka + 9) * 128 + n]);
            __half2 z0 = __floats2half2_rn(W[(size_t)kb * 128 + n],       W[(size_t)(kb + 1) * 128 + n]);
            __half2 w0 = __floats2half2_rn(W[(size_t)(kb + 8) * 128 + n], W[(size_t)(kb + 9) * 128 + n]);
            uint4 cell;
            cell.x = *(unsigned*)&x0; cell.y = *(unsigned*)&y0;
            cell.z = *(unsigned*)&z0; cell.w = *(unsigned*)&w0;
            g_Wiv[l * 2560 + n * 20 + c] = cell;
        }
    }
}

// ---------------- single-kernel scan (decoupled lookback, 98 blocks) -----------
#define SCAN_CHUNK 1024
#define SCAN_PARTS ((NN + SCAN_CHUNK - 1) / SCAN_CHUNK)

__global__ void k_scan() {
    __shared__ int s[SCAN_CHUNK];
    __shared__ int sbase;
    int t = threadIdx.x;
    int bid = blockIdx.x;
    int i = bid * SCAN_CHUNK + t;
    int v = 0;
    if (i < NN) {
        v = g_deg[i] + 1;
        g_dinv[i] = rsqrtf((float)v);
    }
    s[t] = v; __syncthreads();
    for (int off = 1; off < SCAN_CHUNK; off <<= 1) {
        int x = (t >= off) ? s[t - off] : 0;
        __syncthreads();
        s[t] += x;
        __syncthreads();
    }
    if (t == 0) {
        sbase = 0;
        g_aggval[bid] = s[SCAN_CHUNK - 1];
        __threadfence();
        g_aggflag[bid] = 1;
        if (bid == 0) {
            int g = 0;
            for (int qq = 0; qq < GG; qq++) {
                g_goff[qq] = g;
                g += g_gcnt[qq];
                g_gcnt[qq] = 0;            // self-clean for next run
            }
            g_goff[GG] = g;
            g_rowoff[NN] = NEDGE;
        }
    }
    __syncthreads();
    if (t < bid) {
        while (g_aggflag[t] == 0) { __nanosleep(64); }
        atomicAdd_block(&sbase, g_aggval[t]);
    }
    __syncthreads();
    if (i < NN) g_rowoff[i] = sbase + s[t] - v;
}

__global__ void k_fill(const int* __restrict__ ei) {
    int idx = blockIdx.x * blockDim.x + threadIdx.x;
    if (idx < 128) g_aggflag[idx] = 0;     // self-clean for next run
    if (idx >= NEDGE) return;
    int s, d;
    if (idx < EE) { s = ei[idx]; d = ei[EE + idx]; }
    else          { s = d = idx - EE; }
    int pos = g_rowoff[d] + atomicAdd(&g_cursor[d], 1);
    float w = g_dinv[s] * g_dinv[d];
    g_cw[pos] = make_int2(s, __float_as_int(w));
}

// ---------------- CSR aggregation (vectorized): Aimg = agg(g_half) --------------
// warp per dst row; half-warp owns the 256B feature row (uint4/lane),
// two edges per warp instruction. fp32 accumulate, no bias (moved to GEMM).
__device__ __forceinline__ void acc8(float* acc, uint4 u, float wt) {
    float2 f0 = __half22float2(*(__half2*)&u.x);
    float2 f1 = __half22float2(*(__half2*)&u.y);
    float2 f2 = __half22float2(*(__half2*)&u.z);
    float2 f3 = __half22float2(*(__half2*)&u.w);
    acc[0] = fmaf(wt, f0.x, acc[0]); acc[1] = fmaf(wt, f0.y, acc[1]);
    acc[2] = fmaf(wt, f1.x, acc[2]); acc[3] = fmaf(wt, f1.y, acc[3]);
    acc[4] = fmaf(wt, f2.x, acc[4]); acc[5] = fmaf(wt, f2.y, acc[5]);
    acc[6] = fmaf(wt, f3.x, acc[6]); acc[7] = fmaf(wt, f3.y, acc[7]);
}

__global__ void k_agg() {
    int row = (blockIdx.x * blockDim.x + threadIdx.x) >> 5;
    int lane = threadIdx.x & 31;
    if (row >= NN) return;
    int beg = g_rowoff[row];
    int end = g_rowoff[row + 1];
    int half = lane >> 4, hl = lane & 15;
    const uint4* T4 = (const uint4*)g_half;   // row = 16 uint4
    float acc[8] = {};
    int e = beg;
    for (; e + 3 < end; e += 4) {
        int2 cwA = g_cw[e + half];
        int2 cwB = g_cw[e + 2 + half];
        uint4 uA = __ldg(&T4[(size_t)cwA.x * 16 + hl]);
        uint4 uB = __ldg(&T4[(size_t)cwB.x * 16 + hl]);
        acc8(acc, uA, __int_as_float(cwA.y));
        acc8(acc, uB, __int_as_float(cwB.y));
    }
    for (; e < end; e += 2) {
        bool ok = (e + half) < end;
        int2 cw = ok ? g_cw[e + half] : make_int2(0, 0);
        float wt = ok ? __int_as_float(cw.y) : 0.f;
        uint4 u = __ldg(&T4[(size_t)cw.x * 16 + hl]);
        acc8(acc, u, wt);
    }
    // combine the two half-warps (same cols, disjoint edge subsets)
#pragma unroll
    for (int j = 0; j < 8; j++)
        acc[j] += __shfl_xor_sync(0xFFFFFFFFu, acc[j], 16);
    // redistribute: lane l wants cols 4l..4l+3 (owner hl = l>>1, offset (l&1)*4)
    int srcl = lane >> 1;
    float t0 = __shfl_sync(0xFFFFFFFFu, acc[0], srcl);
    float t1 = __shfl_sync(0xFFFFFFFFu, acc[1], srcl);
    float t2 = __shfl_sync(0xFFFFFFFFu, acc[2], srcl);
    float t3 = __shfl_sync(0xFFFFFFFFu, acc[3], srcl);
    float t4 = __shfl_sync(0xFFFFFFFFu, acc[4], srcl);
    float t5 = __shfl_sync(0xFFFFFFFFu, acc[5], srcl);
    float t6 = __shfl_sync(0xFFFFFFFFu, acc[6], srcl);
    float t7 = __shfl_sync(0xFFFFFFFFu, acc[7], srcl);
    bool odd = (lane & 1);
    float4 r;
    r.x = odd ? t4 : t0; r.y = odd ? t5 : t1;
    r.z = odd ? t6 : t2; r.w = odd ? t7 : t3;
    // assemble this lane's A-image cell via shfl (lane = cell index)
    __half2 h01 = __floats2half2_rn(r.x, r.y);
    __half2 h23 = __floats2half2_rn(r.z, r.w);
    unsigned w01 = *(unsigned*)&h01, w23 = *(unsigned*)&h23;
    int kk = lane >> 2, q = lane & 3;
    int lA = 4 * kk + (q >> 1);
    int lB = lA + 2;
    unsigned a01 = __shfl_sync(0xFFFFFFFFu, w01, lA);
    unsigned a23 = __shfl_sync(0xFFFFFFFFu, w23, lA);
    unsigned b01 = __shfl_sync(0xFFFFFFFFu, w01, lB);
    unsigned b23 = __shfl_sync(0xFFFFFFFFu, w23, lB);
    unsigned wa = (q & 1) ? a23 : a01;
    unsigned wb = (q & 1) ? b23 : b01;
    g_Aimg[(size_t)row * 32 + lane] = make_uint2(wa, wb);
}

// ---------------- tensor-core GEMM (mma.sync fp16) + bias/relu epilogue --------
// block = 128x128 tile, 8 warps 4rg x 2cg, warp = 32x64; A+B both smem-staged.
// mode 0: +bias, relu, write fp16 g_half. mode 1: +bias, write fp32 g_bufB.
#define SM_B_OFF 32768
#define GSM (32768 + 40960)   // 72 KB/CTA; 2 CTAs/SM

#define MMA_F16(C, A0, A1, A2, A3, B0, B1) \
    asm volatile("mma.sync.aligned.m16n8k16.row.col.f32.f16.f16.f32 " \
                 "{%0,%1,%2,%3}, {%4,%5,%6,%7}, {%8,%9}, {%0,%1,%2,%3};" \
                 : "+f"((C)[0]), "+f"((C)[1]), "+f"((C)[2]), "+f"((C)[3]) \
                 : "r"(A0), "r"(A1), "r"(A2), "r"(A3), "r"(B0), "r"(B1))

__global__ void __launch_bounds__(256, 2) k_gemm_mma(int layer,
                                                     const float* __restrict__ bias,
                                                     int mode) {
    extern __shared__ char smem[];
    uint2* sA = (uint2*)smem;                    // 4096 uint2, swizzled cells
    const uint4* pB = (const uint4*)(smem + SM_B_OFF);
    int tid = threadIdx.x;
    int row0 = blockIdx.x << 7;

    // stage B cell image: 2560 uint4 = 40 KB
    {
        const uint4* src = g_Wiv + layer * 2560;
        uint4* dst = (uint4*)(smem + SM_B_OFF);
#pragma unroll
        for (int it = 0; it < 10; it++) {
            int i = it * 256 + tid;
            dst[i] = __ldg(&src[i]);
        }
    }
    // stage A tile: 2048 uint4 = 32 KB, swizzle cell kk ^= row&7
    {
        const uint4* src = (const uint4*)(g_Aimg + (size_t)row0 * 32);
#pragma unroll
        for (int it = 0; it < 8; it++) {
            int i = it * 256 + tid;              // uint4 = 2 cells
            uint4 v = __ldg(&src[i]);
            int r = i >> 4;
            int c2 = (i & 15) * 2;               // even cell index
            int kk = c2 >> 2, q = c2 & 3;        // q in {0,2}
            int dstc = ((kk ^ (r & 7)) << 2) + q;
            *(uint4*)&sA[r * 32 + dstc] = v;
        }
    }
    __syncthreads();

    int lane = tid & 31, warp = tid >> 5;
    int rq = lane >> 2;        // 0..7
    int q = lane & 3;          // 0..3
    int rg = warp >> 1, cg = warp & 1;
    int wr = rg * 32 + rq;
    int ncol0 = cg * 64;

    float c[2][8][4] = {};

    const uint2* aRow0 = sA + (wr +  0) * 32 + q;
    const uint2* aRow1 = sA + (wr +  8) * 32 + q;
    const uint2* aRow2 = sA + (wr + 16) * 32 + q;
    const uint2* aRow3 = sA + (wr + 24) * 32 + q;
    const uint4* bBase = pB + (ncol0 + rq) * 20 + q;

#pragma unroll
    for (int j = 0; j < 4; j++) {
        int swa = ((2 * j) ^ rq) << 2;
        int swb = ((2 * j + 1) ^ rq) << 2;
        uint2 Aa0 = aRow0[swa], Aa1 = aRow1[swa];
        uint2 Aa2 = aRow2[swa], Aa3 = aRow3[swa];
        uint2 Ab0 = aRow0[swb], Ab1 = aRow1[swb];
        uint2 Ab2 = aRow2[swb], Ab3 = aRow3[swb];
        const uint4* bp = bBase + j * 4;
#pragma unroll
        for (int t = 0; t < 8; t++) {
            uint4 B = bp[t * 8 * 20];
            MMA_F16(c[0][t], Aa0.x, Aa1.x, Aa0.y, Aa1.y, B.x, B.y);
            MMA_F16(c[1][t], Aa2.x, Aa3.x, Aa2.y, Aa3.y, B.x, B.y);
            MMA_F16(c[0][t], Ab0.x, Ab1.x, Ab0.y, Ab1.y, B.z, B.w);
            MMA_F16(c[1][t], Ab2.x, Ab3.x, Ab2.y, Ab3.y, B.z, B.w);
        }
    }

    // epilogue: + bias, optional relu, fp16 or fp32 stores
    unsigned short* gh = (unsigned short*)g_half;
    int wrow = row0 + rg * 32;
#pragma unroll
    for (int mb = 0; mb < 2; mb++) {
        int r1 = wrow + mb * 16 + rq, r2 = r1 + 8;
#pragma unroll
        for (int t = 0; t < 8; t++) {
            int col = ncol0 + t * 8 + q * 2;
            float2 bb = *(const float2*)(bias + col);
            float v0 = c[mb][t][0] + bb.x, v1 = c[mb][t][1] + bb.y;
            float v2 = c[mb][t][2] + bb.x, v3 = c[mb][t][3] + bb.y;
            if (mode == 0) {
                v0 = fmaxf(v0, 0.f); v1 = fmaxf(v1, 0.f);
                v2 = fmaxf(v2, 0.f); v3 = fmaxf(v3, 0.f);
                if (r1 < NN) {
                    __half2 h = __floats2half2_rn(v0, v1);
                    *(unsigned*)(gh + (size_t)r1 * 128 + col) = *(unsigned*)&h;
                }
                if (r2 < NN) {
                    __half2 h = __floats2half2_rn(v2, v3);
                    *(unsigned*)(gh + (size_t)r2 * 128 + col) = *(unsigned*)&h;
                }
            } else {
                if (r1 < NN) *(float2*)(g_bufB + (size_t)r1 * 128 + col) = make_float2(v0, v1);
                if (r2 < NN) *(float2*)(g_bufB + (size_t)r2 * 128 + col) = make_float2(v2, v3);
            }
        }
    }
}

// ---------------- pooling (+ deg cleanup for next run) --------------------------
__global__ void k_pool() {
    int gid = blockIdx.x * 128 + threadIdx.x;
    for (int i = gid; i < NN; i += 512 * 128) { g_deg[i] = 0; }
    int g = blockIdx.x >> 3;
    int s = blockIdx.x & 7;
    int col = threadIdx.x;
    int start = g_goff[g];
    int cnt = g_goff[g + 1] - start;
    int chunk = (cnt + 7) >> 3;
    int lo = start + s * chunk;
    int hi = lo + chunk;
    int ge = start + cnt;
    if (hi > ge) hi = ge;
    float sum = 0.f;
    int i = lo;
    for (; i + 3 < hi; i += 4) {
        sum += g_bufB[(size_t)(i + 0) * 128 + col];
        sum += g_bufB[(size_t)(i + 1) * 128 + col];
        sum += g_bufB[(size_t)(i + 2) * 128 + col];
        sum += g_bufB[(size_t)(i + 3) * 128 + col];
    }
    for (; i < hi; i++) sum += g_bufB[(size_t)i * 128 + col];
    if (lo < hi) atomicAdd(&g_pool[g * 128 + col], sum);
}

// ---------------- MLP head (+ pool cleanup for next run) ------------------------
__global__ void k_mlp(const float* __restrict__ Wo1, const float* __restrict__ bo1,
                      const float* __restrict__ Wo2, const float* __restrict__ bo2,
                      float* __restrict__ out) {
    __shared__ float ps[128];
    __shared__ float zs[64];
    int g = blockIdx.x;
    int t = threadIdx.x;
    int cnt = g_goff[g + 1] - g_goff[g];
    float inv = 1.0f / fmaxf((float)cnt, 1.0f);
    ps[t]      = g_pool[g * 128 + t] * inv;
    ps[t + 64] = g_pool[g * 128 + t + 64] * inv;
    g_pool[g * 128 + t] = 0.f;          // self-clean for next run
    g_pool[g * 128 + t + 64] = 0.f;
    __syncthreads();
    float z = bo1[t];
#pragma unroll 8
    for (int k = 0; k < 128; k++) z = fmaf(ps[k], Wo1[k * 64 + t], z);
    zs[t] = fmaxf(z, 0.f);
    __syncthreads();
    if (t < OUTD) {
        float o = bo2[t];
#pragma unroll 8
        for (int j = 0; j < 64; j++) o = fmaf(zs[j], Wo2[j * 32 + t], o);
        out[g * OUTD + t] = o;
    }
}

// ---------------- launch ------------------------------------------------------------
extern "C" void kernel_launch(void* const* d_in, const int* in_sizes, int n_in,
                              void* d_out, int out_size) {
    const float* x    = (const float*)d_in[0];
    const int*   ei   = (const int*)d_in[1];
    const int*   batch= (const int*)d_in[2];
    const float* W1   = (const float*)d_in[3];
    const float* b1   = (const float*)d_in[4];
    const float* W2   = (const float*)d_in[5];
    const float* b2   = (const float*)d_in[6];
    const float* W3   = (const float*)d_in[7];
    const float* b3   = (const float*)d_in[8];
    const float* Wo1  = (const float*)d_in[9];
    const float* bo1  = (const float*)d_in[10];
    const float* Wo2  = (const float*)d_in[11];
    const float* bo2  = (const float*)d_in[12];
    float* out = (float*)d_out;

    cudaFuncSetAttribute(k_gemm_mma, cudaFuncAttributeMaxDynamicSharedMemorySize, GSM);

    const int PREP_TASKS = NN * 32 + 3 * 2048;
    const int GEMM_BLOCKS = (NN + 127) / 128;
    const int AGG_BLOCKS  = (NN + 7) / 8;

    k_prep<<<(PREP_TASKS + 255) / 256, 256>>>(x, ei, batch, W1, W2, W3);  // 0
    k_scan<<<SCAN_PARTS, SCAN_CHUNK>>>();                                 // 1
    k_fill<<<(NEDGE + 255) / 256, 256>>>(ei);                             // 2
    k_agg<<<AGG_BLOCKS, 256>>>();                                         // 3 <- ncu slot
    k_gemm_mma<<<GEMM_BLOCKS, 256, GSM>>>(0, b1, 0);                      // 4
    k_agg<<<AGG_BLOCKS, 256>>>();                                         // 5
    k_gemm_mma<<<GEMM_BLOCKS, 256, GSM>>>(1, b2, 0);                      // 6
    k_agg<<<AGG_BLOCKS, 256>>>();                                         // 7
    k_gemm_mma<<<GEMM_BLOCKS, 256, GSM>>>(2, b3, 1);                      // 8
    k_pool<<<GG * 8, 128>>>();                                            // 9
    k_mlp<<<GG, 64>>>(Wo1, bo1, Wo2, bo2, out);                           // 10
}